// round 2
// baseline (speedup 1.0000x reference)
#include <cuda_runtime.h>
#include <cstdint>

#define N_NODES 10000
#define N_EDGES 320000
#define F_IN 512
#define HID 256

// ---------------- device scratch (static, no allocation) ----------------
__device__ __align__(16) float g_deg[N_NODES];
__device__ __align__(16) float g_norm[N_EDGES];
__device__ __align__(16) float g_H0[(size_t)N_NODES * HID];    // feature @ W1 + b1
__device__ __align__(16) float g_AGG1[(size_t)N_NODES * HID];  // aggregated layer 1
__device__ __align__(16) float g_Z[N_NODES * 2];               // relu(AGG1) @ W2 + b2
__device__ __align__(16) float g_U[N_NODES * 2];               // aggregated layer 2

// ---------------- zero scratch that must start at 0 each replay ----------------
__global__ void zero_kernel() {
    const size_t T0 = N_NODES;                       // deg
    const size_t T1 = T0 + (size_t)N_NODES * HID;    // AGG1
    const size_t T2 = T1 + N_NODES * 2;              // U
    size_t i = (size_t)blockIdx.x * blockDim.x + threadIdx.x;
    size_t stride = (size_t)gridDim.x * blockDim.x;
    for (; i < T2; i += stride) {
        if (i < T0) g_deg[i] = 0.0f;
        else if (i < T1) g_AGG1[i - T0] = 0.0f;
        else g_U[i - T1] = 0.0f;
    }
}

// ---------------- degree ----------------
__global__ void deg_kernel(const int* __restrict__ ei) {
    int e = blockIdx.x * blockDim.x + threadIdx.x;
    if (e >= N_EDGES) return;
    int d = ei[N_EDGES + e];
    atomicAdd(&g_deg[d], 1.0f);
}

// ---------------- per-edge norm = rsqrt(deg[s]*deg[d]) ----------------
__global__ void norm_kernel(const int* __restrict__ ei) {
    int e = blockIdx.x * blockDim.x + threadIdx.x;
    if (e >= N_EDGES) return;
    int s = ei[e];
    int d = ei[N_EDGES + e];
    float ds = fmaxf(g_deg[s], 1.0f);
    float dd = fmaxf(g_deg[d], 1.0f);
    g_norm[e] = rsqrtf(ds * dd);
}

// ---------------- SGEMM: H0 = feature[10000,512] @ W1[512,256] + b1 ----------------
#define BM 128
#define BN 64
#define BK 16
#define TM 8
#define TN 4
// 256 threads: 16 (rows) x 16 (cols)

__global__ __launch_bounds__(256) void gemm1_kernel(
    const float* __restrict__ A,   // [M, K] = [10000, 512]
    const float* __restrict__ B,   // [K, N] = [512, 256]
    const float* __restrict__ bias // [256]
) {
    __shared__ float As[BK][BM + 4];
    __shared__ float Bs[BK][BN + 4];
    const int M = N_NODES, K = F_IN, NN = HID;

    int bm = blockIdx.y * BM;
    int bn = blockIdx.x * BN;
    int tid = threadIdx.x;
    int tcol = tid & 15;   // 0..15  -> 4 output cols each
    int trow = tid >> 4;   // 0..15  -> 8 output rows each

    float acc[TM][TN] = {};

    for (int k0 = 0; k0 < K; k0 += BK) {
        // load A tile: 128 rows x 16 cols = 512 float4; 2 per thread
        #pragma unroll
        for (int i = 0; i < 2; i++) {
            int f = tid + 256 * i;
            int r = f >> 2;        // tile row 0..127
            int c4 = f & 3;        // which float4 of the 16-wide K slice
            int grow = bm + r;
            float4 v = make_float4(0.f, 0.f, 0.f, 0.f);
            if (grow < M)
                v = *(const float4*)(A + (size_t)grow * K + k0 + c4 * 4);
            As[c4 * 4 + 0][r] = v.x;
            As[c4 * 4 + 1][r] = v.y;
            As[c4 * 4 + 2][r] = v.z;
            As[c4 * 4 + 3][r] = v.w;
        }
        // load B tile: 16 rows x 64 cols = 256 float4; 1 per thread
        {
            int r = tid >> 4;      // 0..15
            int c4 = tid & 15;     // 0..15
            float4 v = *(const float4*)(B + (size_t)(k0 + r) * NN + bn + c4 * 4);
            *(float4*)(&Bs[r][c4 * 4]) = v;
        }
        __syncthreads();

        #pragma unroll
        for (int k = 0; k < BK; k++) {
            float4 b4 = *(const float4*)(&Bs[k][tcol * 4]);
            float4 a0 = *(const float4*)(&As[k][trow * 8]);
            float4 a1 = *(const float4*)(&As[k][trow * 8 + 4]);
            float am[TM] = {a0.x, a0.y, a0.z, a0.w, a1.x, a1.y, a1.z, a1.w};
            float bm4[TN] = {b4.x, b4.y, b4.z, b4.w};
            #pragma unroll
            for (int i = 0; i < TM; i++)
                #pragma unroll
                for (int j = 0; j < TN; j++)
                    acc[i][j] += am[i] * bm4[j];
        }
        __syncthreads();
    }

    // store with bias
    float4 bv = *(const float4*)(bias + bn + tcol * 4);
    #pragma unroll
    for (int i = 0; i < TM; i++) {
        int grow = bm + trow * TM + i;
        if (grow < M) {
            float4 o;
            o.x = acc[i][0] + bv.x;
            o.y = acc[i][1] + bv.y;
            o.z = acc[i][2] + bv.z;
            o.w = acc[i][3] + bv.w;
            *(float4*)(g_H0 + (size_t)grow * NN + bn + tcol * 4) = o;
        }
    }
}

// ---------------- agg1: AGG1[dst] += H0[src] * norm[e], 256 channels ----------------
__device__ __forceinline__ void red_add_v4(float* addr, float x, float y, float z, float w) {
    asm volatile("red.global.add.v4.f32 [%0], {%1,%2,%3,%4};"
                 :: "l"(addr), "f"(x), "f"(y), "f"(z), "f"(w) : "memory");
}

__global__ __launch_bounds__(256) void agg1_kernel(const int* __restrict__ ei) {
    int gw = (blockIdx.x * blockDim.x + threadIdx.x) >> 5;
    int lane = threadIdx.x & 31;
    if (gw >= N_EDGES) return;
    int s = ei[gw];
    int d = ei[N_EDGES + gw];
    float nm = g_norm[gw];
    const float4* srcRow = (const float4*)(g_H0 + (size_t)s * HID);
    float* dstRow = g_AGG1 + (size_t)d * HID;
    #pragma unroll
    for (int j = 0; j < 2; j++) {
        int idx4 = lane + 32 * j;           // float4 index 0..63
        float4 v = srcRow[idx4];
        red_add_v4(dstRow + idx4 * 4, v.x * nm, v.y * nm, v.z * nm, v.w * nm);
    }
}

// ---------------- Z = relu(AGG1) @ W2 + b2  (warp per node) ----------------
__global__ __launch_bounds__(256) void z_kernel(const float* __restrict__ W2,
                                                const float* __restrict__ b2) {
    int gw = (blockIdx.x * blockDim.x + threadIdx.x) >> 5;
    int lane = threadIdx.x & 31;
    if (gw >= N_NODES) return;
    const float* row = g_AGG1 + (size_t)gw * HID;
    float s0 = 0.f, s1 = 0.f;
    #pragma unroll
    for (int t = 0; t < 8; t++) {
        int idx = lane + 32 * t;
        float x = fmaxf(row[idx], 0.f);
        s0 += x * __ldg(&W2[idx * 2 + 0]);
        s1 += x * __ldg(&W2[idx * 2 + 1]);
    }
    #pragma unroll
    for (int o = 16; o; o >>= 1) {
        s0 += __shfl_down_sync(0xFFFFFFFFu, s0, o);
        s1 += __shfl_down_sync(0xFFFFFFFFu, s1, o);
    }
    if (lane == 0) {
        g_Z[2 * gw + 0] = s0 + b2[0];
        g_Z[2 * gw + 1] = s1 + b2[1];
    }
}

// ---------------- agg2: U[dst] += Z[src] * norm[e], 2 channels ----------------
__device__ __forceinline__ void red_add_v2(float* addr, float x, float y) {
    asm volatile("red.global.add.v2.f32 [%0], {%1,%2};"
                 :: "l"(addr), "f"(x), "f"(y) : "memory");
}

__global__ void agg2_kernel(const int* __restrict__ ei) {
    int e = blockIdx.x * blockDim.x + threadIdx.x;
    if (e >= N_EDGES) return;
    int s = ei[e];
    int d = ei[N_EDGES + e];
    float nm = g_norm[e];
    float z0 = g_Z[2 * s] * nm;
    float z1 = g_Z[2 * s + 1] * nm;
    red_add_v2(g_U + 2 * d, z0, z1);
}

// ---------------- final hyperbolic lift + Poincare projection ----------------
__global__ void final_kernel(const float* __restrict__ scale, float* __restrict__ out) {
    int n = blockIdx.x * blockDim.x + threadIdx.x;
    if (n >= N_NODES) return;
    float u0 = g_U[2 * n], u1 = g_U[2 * n + 1];
    float un = sqrtf(u0 * u0 + u1 * u1);
    un = fmaxf(un, 1e-15f);
    float ch = coshf(un);
    float sh = sinhf(un);
    // p = (sinh(un) * u/un) / (1 + cosh(un))
    float inv = 1.0f / (un * (1.0f + ch));
    float p0 = sh * u0 * inv;
    float p1 = sh * u1 * inv;
    // normalize to clamped scale
    float pn = fmaxf(sqrtf(p0 * p0 + p1 * p1), 1e-12f);
    const float MIN_SCALE = 2.0f * (0.999f / 3.0f);
    const float MAX_SCALE = 0.999f;
    float s = fminf(fmaxf(scale[0], MIN_SCALE), MAX_SCALE);
    p0 = p0 / pn * s;
    p1 = p1 / pn * s;
    // project onto ball (no-op for s <= maxnorm, kept for fidelity)
    float nrm = fmaxf(sqrtf(p0 * p0 + p1 * p1), 1e-15f);
    float maxnorm = 1.0f - 1e-15f;
    if (nrm > maxnorm) {
        p0 = p0 / nrm * maxnorm;
        p1 = p1 / nrm * maxnorm;
    }
    out[2 * n + 0] = p0;
    out[2 * n + 1] = p1;
}

// ---------------- launch ----------------
extern "C" void kernel_launch(void* const* d_in, const int* in_sizes, int n_in,
                              void* d_out, int out_size) {
    const float* feature = (const float*)d_in[0];
    const int* ei = (const int*)d_in[1];      // JAX default: int64 silently -> int32
    const float* W1 = (const float*)d_in[2];
    const float* b1 = (const float*)d_in[3];
    const float* W2 = (const float*)d_in[4];
    const float* b2 = (const float*)d_in[5];
    const float* scale = (const float*)d_in[6];
    float* out = (float*)d_out;

    // zero deg / AGG1 / U
    {
        const size_t total = N_NODES + (size_t)N_NODES * HID + N_NODES * 2;
        int blocks = (int)((total + 255) / 256);
        zero_kernel<<<blocks, 256>>>();
    }
    // degree
    deg_kernel<<<(N_EDGES + 255) / 256, 256>>>(ei);
    // per-edge norm
    norm_kernel<<<(N_EDGES + 255) / 256, 256>>>(ei);
    // GEMM1
    {
        dim3 grid(HID / BN, (N_NODES + BM - 1) / BM);
        gemm1_kernel<<<grid, 256>>>(feature, W1, b1);
    }
    // aggregate layer 1 (one warp per edge)
    {
        long long threads = (long long)N_EDGES * 32;
        int blocks = (int)((threads + 255) / 256);
        agg1_kernel<<<blocks, 256>>>(ei);
    }
    // Z = relu(AGG1) @ W2 + b2 (one warp per node)
    {
        long long threads = (long long)N_NODES * 32;
        int blocks = (int)((threads + 255) / 256);
        z_kernel<<<blocks, 256>>>(W2, b2);
    }
    // aggregate layer 2
    agg2_kernel<<<(N_EDGES + 255) / 256, 256>>>(ei);
    // final lift + projection
    final_kernel<<<(N_NODES + 255) / 256, 256>>>(scale, out);
}

// round 3
// speedup vs baseline: 1.0121x; 1.0121x over previous
#include <cuda_runtime.h>
#include <cstdint>

#define N_NODES 10000
#define N_EDGES 320000
#define F_IN 512
#define HID 256

// ---------------- device scratch (static, no allocation) ----------------
__device__ __align__(16) int   g_cnt[N_NODES];       // indegree (histogram of dst)
__device__ __align__(16) int   g_off[N_NODES];       // exclusive prefix of g_cnt
__device__ __align__(16) int   g_fill[N_NODES];      // scatter fill counters
__device__ __align__(16) int   g_csr_src[N_EDGES];   // src ids grouped by dst
__device__ __align__(16) float g_csr_nrm[N_EDGES];   // per-edge norm grouped by dst
__device__ __align__(16) float g_H0[(size_t)N_NODES * HID];  // feature @ W1 + b1
__device__ __align__(16) float g_Z[N_NODES * 2];             // relu(AGG1) @ W2 + b2

// ---------------- zero counters ----------------
__global__ void zero_kernel() {
    int i = blockIdx.x * blockDim.x + threadIdx.x;
    if (i < N_NODES) {
        g_cnt[i] = 0;
        g_fill[i] = 0;
    }
}

// ---------------- indegree histogram ----------------
__global__ void deg_kernel(const int* __restrict__ ei) {
    int e = blockIdx.x * blockDim.x + threadIdx.x;
    if (e >= N_EDGES) return;
    atomicAdd(&g_cnt[ei[N_EDGES + e]], 1);
}

// ---------------- single-block exclusive scan over g_cnt -> g_off ----------------
#define SCAN_THREADS 1024
#define SCAN_CHUNK 10   // 1024*10 = 10240 >= 10000
__global__ __launch_bounds__(SCAN_THREADS) void scan_kernel() {
    __shared__ int partial[SCAN_THREADS];
    int tid = threadIdx.x;
    int base = tid * SCAN_CHUNK;
    int local[SCAN_CHUNK];
    int sum = 0;
    #pragma unroll
    for (int i = 0; i < SCAN_CHUNK; i++) {
        int idx = base + i;
        int v = (idx < N_NODES) ? g_cnt[idx] : 0;
        local[i] = sum;          // exclusive within thread
        sum += v;
    }
    partial[tid] = sum;
    __syncthreads();
    // Hillis-Steele inclusive scan over partials
    for (int off = 1; off < SCAN_THREADS; off <<= 1) {
        int v = 0;
        if (tid >= off) v = partial[tid - off];
        __syncthreads();
        if (tid >= off) partial[tid] += v;
        __syncthreads();
    }
    int prev = (tid == 0) ? 0 : partial[tid - 1];
    #pragma unroll
    for (int i = 0; i < SCAN_CHUNK; i++) {
        int idx = base + i;
        if (idx < N_NODES) g_off[idx] = prev + local[i];
    }
}

// ---------------- scatter edges into CSR (by dst), with per-edge norm ----------------
__global__ void scatter_kernel(const int* __restrict__ ei) {
    int e = blockIdx.x * blockDim.x + threadIdx.x;
    if (e >= N_EDGES) return;
    int s = ei[e];
    int d = ei[N_EDGES + e];
    float ds = fmaxf((float)g_cnt[s], 1.0f);
    float dd = fmaxf((float)g_cnt[d], 1.0f);
    float nm = rsqrtf(ds * dd);
    int pos = g_off[d] + atomicAdd(&g_fill[d], 1);
    g_csr_src[pos] = s;
    g_csr_nrm[pos] = nm;
}

// ---------------- SGEMM: H0 = feature[10000,512] @ W1[512,256] + b1 ----------------
#define BM 128
#define BN 128
#define BK 16
#define TM 8
#define TN 8
// 256 threads: 16 (rows) x 16 (cols), each thread computes 8x8

__global__ __launch_bounds__(256, 2) void gemm1_kernel(
    const float* __restrict__ A,   // [M, K] = [10000, 512]
    const float* __restrict__ B,   // [K, N] = [512, 256]
    const float* __restrict__ bias // [256]
) {
    __shared__ float As[BK][BM + 4];
    __shared__ float Bs[BK][BN + 4];
    const int M = N_NODES, K = F_IN, NN = HID;

    int bm = blockIdx.y * BM;
    int bn = blockIdx.x * BN;
    int tid = threadIdx.x;
    int tcol = tid & 15;   // 0..15 -> 8 output cols each
    int trow = tid >> 4;   // 0..15 -> 8 output rows each

    float acc[TM][TN] = {};

    for (int k0 = 0; k0 < K; k0 += BK) {
        // load A tile: 128 rows x 16 K = 512 float4; 2 per thread (transposed store)
        #pragma unroll
        for (int i = 0; i < 2; i++) {
            int f = tid + 256 * i;
            int r = f >> 2;        // tile row 0..127
            int c4 = f & 3;        // which float4 of the 16-wide K slice
            int grow = bm + r;
            float4 v = make_float4(0.f, 0.f, 0.f, 0.f);
            if (grow < M)
                v = *(const float4*)(A + (size_t)grow * K + k0 + c4 * 4);
            As[c4 * 4 + 0][r] = v.x;
            As[c4 * 4 + 1][r] = v.y;
            As[c4 * 4 + 2][r] = v.z;
            As[c4 * 4 + 3][r] = v.w;
        }
        // load B tile: 16 K-rows x 128 cols = 512 float4; 2 per thread
        #pragma unroll
        for (int i = 0; i < 2; i++) {
            int f = tid + 256 * i;
            int r = f >> 5;        // 0..15
            int c4 = f & 31;       // 0..31
            float4 v = *(const float4*)(B + (size_t)(k0 + r) * NN + bn + c4 * 4);
            *(float4*)(&Bs[r][c4 * 4]) = v;
        }
        __syncthreads();

        #pragma unroll
        for (int k = 0; k < BK; k++) {
            float4 a0 = *(const float4*)(&As[k][trow * 8]);
            float4 a1 = *(const float4*)(&As[k][trow * 8 + 4]);
            float4 b0 = *(const float4*)(&Bs[k][tcol * 8]);
            float4 b1 = *(const float4*)(&Bs[k][tcol * 8 + 4]);
            float am[TM] = {a0.x, a0.y, a0.z, a0.w, a1.x, a1.y, a1.z, a1.w};
            float bv[TN] = {b0.x, b0.y, b0.z, b0.w, b1.x, b1.y, b1.z, b1.w};
            #pragma unroll
            for (int i = 0; i < TM; i++)
                #pragma unroll
                for (int j = 0; j < TN; j++)
                    acc[i][j] += am[i] * bv[j];
        }
        __syncthreads();
    }

    // store with bias
    float4 bva = *(const float4*)(bias + bn + tcol * 8);
    float4 bvb = *(const float4*)(bias + bn + tcol * 8 + 4);
    float bb[TN] = {bva.x, bva.y, bva.z, bva.w, bvb.x, bvb.y, bvb.z, bvb.w};
    #pragma unroll
    for (int i = 0; i < TM; i++) {
        int grow = bm + trow * TM + i;
        if (grow < M) {
            float4 o0, o1;
            o0.x = acc[i][0] + bb[0]; o0.y = acc[i][1] + bb[1];
            o0.z = acc[i][2] + bb[2]; o0.w = acc[i][3] + bb[3];
            o1.x = acc[i][4] + bb[4]; o1.y = acc[i][5] + bb[5];
            o1.z = acc[i][6] + bb[6]; o1.w = acc[i][7] + bb[7];
            *(float4*)(g_H0 + (size_t)grow * NN + bn + tcol * 8) = o0;
            *(float4*)(g_H0 + (size_t)grow * NN + bn + tcol * 8 + 4) = o1;
        }
    }
}

// ---------------- fused agg1 + relu + W2 + b2 -> Z  (warp per dst node) ----------------
__global__ __launch_bounds__(256) void fusedZ_kernel(const float* __restrict__ W2,
                                                     const float* __restrict__ b2) {
    int gw = (blockIdx.x * blockDim.x + threadIdx.x) >> 5;
    int lane = threadIdx.x & 31;
    if (gw >= N_NODES) return;

    int start = g_off[gw];
    int end = start + g_cnt[gw];

    // preload this lane's W2 rows: channels 4*lane..+3 and 128+4*lane..+3
    int cA = 4 * lane;
    int cB = 128 + 4 * lane;
    float w0a[4], w1a[4], w0b[4], w1b[4];
    #pragma unroll
    for (int j = 0; j < 4; j++) {
        w0a[j] = __ldg(&W2[(cA + j) * 2 + 0]);
        w1a[j] = __ldg(&W2[(cA + j) * 2 + 1]);
        w0b[j] = __ldg(&W2[(cB + j) * 2 + 0]);
        w1b[j] = __ldg(&W2[(cB + j) * 2 + 1]);
    }

    float acc[8] = {};
    int p = start;
    // unroll by 2 for MLP
    for (; p + 1 < end; p += 2) {
        int s0 = g_csr_src[p];
        int s1 = g_csr_src[p + 1];
        float n0 = g_csr_nrm[p];
        float n1 = g_csr_nrm[p + 1];
        const float4* r0 = (const float4*)(g_H0 + (size_t)s0 * HID);
        const float4* r1 = (const float4*)(g_H0 + (size_t)s1 * HID);
        float4 a0 = r0[lane], a1 = r0[lane + 32];
        float4 b0 = r1[lane], b1 = r1[lane + 32];
        acc[0] += a0.x * n0 + b0.x * n1;
        acc[1] += a0.y * n0 + b0.y * n1;
        acc[2] += a0.z * n0 + b0.z * n1;
        acc[3] += a0.w * n0 + b0.w * n1;
        acc[4] += a1.x * n0 + b1.x * n1;
        acc[5] += a1.y * n0 + b1.y * n1;
        acc[6] += a1.z * n0 + b1.z * n1;
        acc[7] += a1.w * n0 + b1.w * n1;
    }
    if (p < end) {
        int s0 = g_csr_src[p];
        float n0 = g_csr_nrm[p];
        const float4* r0 = (const float4*)(g_H0 + (size_t)s0 * HID);
        float4 a0 = r0[lane], a1 = r0[lane + 32];
        acc[0] += a0.x * n0; acc[1] += a0.y * n0;
        acc[2] += a0.z * n0; acc[3] += a0.w * n0;
        acc[4] += a1.x * n0; acc[5] += a1.y * n0;
        acc[6] += a1.z * n0; acc[7] += a1.w * n0;
    }

    // relu + dot with W2
    float z0 = 0.f, z1 = 0.f;
    #pragma unroll
    for (int j = 0; j < 4; j++) {
        float xa = fmaxf(acc[j], 0.f);
        float xb = fmaxf(acc[4 + j], 0.f);
        z0 += xa * w0a[j] + xb * w0b[j];
        z1 += xa * w1a[j] + xb * w1b[j];
    }
    #pragma unroll
    for (int o = 16; o; o >>= 1) {
        z0 += __shfl_down_sync(0xFFFFFFFFu, z0, o);
        z1 += __shfl_down_sync(0xFFFFFFFFu, z1, o);
    }
    if (lane == 0) {
        g_Z[2 * gw + 0] = z0 + b2[0];
        g_Z[2 * gw + 1] = z1 + b2[1];
    }
}

// ---------------- fused agg2 + hyperbolic lift + Poincare projection ----------------
__global__ __launch_bounds__(256) void fusedU_kernel(const float* __restrict__ scale,
                                                     float* __restrict__ out) {
    int gw = (blockIdx.x * blockDim.x + threadIdx.x) >> 5;
    int lane = threadIdx.x & 31;
    if (gw >= N_NODES) return;

    int start = g_off[gw];
    int end = start + g_cnt[gw];

    float u0 = 0.f, u1 = 0.f;
    for (int p = start + lane; p < end; p += 32) {
        int s = g_csr_src[p];
        float nm = g_csr_nrm[p];
        float2 z = *(const float2*)(g_Z + 2 * s);
        u0 += z.x * nm;
        u1 += z.y * nm;
    }
    #pragma unroll
    for (int o = 16; o; o >>= 1) {
        u0 += __shfl_down_sync(0xFFFFFFFFu, u0, o);
        u1 += __shfl_down_sync(0xFFFFFFFFu, u1, o);
    }
    if (lane == 0) {
        float un = sqrtf(u0 * u0 + u1 * u1);
        un = fmaxf(un, 1e-15f);
        float ch = coshf(un);
        float sh = sinhf(un);
        float inv = 1.0f / (un * (1.0f + ch));
        float p0 = sh * u0 * inv;
        float p1 = sh * u1 * inv;
        float pn = fmaxf(sqrtf(p0 * p0 + p1 * p1), 1e-12f);
        const float MIN_SCALE = 2.0f * (0.999f / 3.0f);
        const float MAX_SCALE = 0.999f;
        float s = fminf(fmaxf(scale[0], MIN_SCALE), MAX_SCALE);
        p0 = p0 / pn * s;
        p1 = p1 / pn * s;
        float nrm = fmaxf(sqrtf(p0 * p0 + p1 * p1), 1e-15f);
        float maxnorm = 1.0f - 1e-15f;
        if (nrm > maxnorm) {
            p0 = p0 / nrm * maxnorm;
            p1 = p1 / nrm * maxnorm;
        }
        out[2 * gw + 0] = p0;
        out[2 * gw + 1] = p1;
    }
}

// ---------------- launch ----------------
extern "C" void kernel_launch(void* const* d_in, const int* in_sizes, int n_in,
                              void* d_out, int out_size) {
    const float* feature = (const float*)d_in[0];
    const int* ei = (const int*)d_in[1];      // JAX default x32: edge_index is int32
    const float* W1 = (const float*)d_in[2];
    const float* b1 = (const float*)d_in[3];
    const float* W2 = (const float*)d_in[4];
    const float* b2 = (const float*)d_in[5];
    const float* scale = (const float*)d_in[6];
    float* out = (float*)d_out;

    zero_kernel<<<(N_NODES + 255) / 256, 256>>>();
    deg_kernel<<<(N_EDGES + 255) / 256, 256>>>(ei);
    scan_kernel<<<1, SCAN_THREADS>>>();
    scatter_kernel<<<(N_EDGES + 255) / 256, 256>>>(ei);
    {
        dim3 grid(HID / BN, (N_NODES + BM - 1) / BM);  // (2, 79)
        gemm1_kernel<<<grid, 256>>>(feature, W1, b1);
    }
    {
        int warps = N_NODES;
        int blocks = (warps * 32 + 255) / 256;
        fusedZ_kernel<<<blocks, 256>>>(W2, b2);
        fusedU_kernel<<<blocks, 256>>>(scale, out);
    }
}